// round 10
// baseline (speedup 1.0000x reference)
#include <cuda_runtime.h>
#include <cuda_fp16.h>
#include <cstdint>
#include <cstddef>

// ---------------- problem constants ----------------
#define M_DIM 8192
#define K_DIM 7168
#define N_DIM 2112           // 1536 + 512 + 64
#define Q_RANK 1536
#define KV_RANK 512
#define ROPE_DIM 64
#define N_GROUPS 12
#define FP8_MAX 448.0f
#define EPS_RMS 1e-6f

#define OUT_QQ   ((size_t)0)
#define OUT_SC   ((size_t)M_DIM * Q_RANK)
#define OUT_KV   (OUT_SC + (size_t)M_DIM * N_GROUPS)
#define OUT_KPE  (OUT_KV + (size_t)M_DIM * KV_RANK)

// ---------------- GEMM tiling ----------------
#define MT 256
#define NT 128
#define KB 64                        // fp16 elems per K slab (128 bytes per row)
#define NSLAB (K_DIM / KB)           // 112
#define N_PAD 2176                   // 17 * 128
#define STAGE_BYTES (80 * 1024)      // Ahi 32K | Alo 32K | Bhi 16K
#define NSTAGE 2
#define SMEM_TOTAL (NSTAGE * STAGE_BYTES)   // 160 KB, 1 CTA/SM

// ---------------- device scratch (no cudaMalloc allowed) ----------------
__device__ __align__(1024) __half g_Ahi[(size_t)M_DIM * K_DIM];
__device__ __align__(1024) __half g_Alo[(size_t)M_DIM * K_DIM];
__device__ __align__(1024) __half g_Bhi[(size_t)N_PAD * K_DIM];   // [n][k] transposed
__device__ __align__(16)   float  g_scratch[(size_t)M_DIM * N_DIM];

// ---------------- PTX helpers (baseline PTX only: sm_80-era) ----------------
__device__ __forceinline__ uint32_t smem_u32(const void* p) {
    uint32_t a;
    asm("{ .reg .u64 t; cvta.to.shared.u64 t, %1; cvt.u32.u64 %0, t; }" : "=r"(a) : "l"(p));
    return a;
}

__device__ __forceinline__ void cpa16(uint32_t dst, const void* src) {
    asm volatile("cp.async.cg.shared.global [%0], [%1], 16;" :: "r"(dst), "l"(src));
}
#define CP_COMMIT() asm volatile("cp.async.commit_group;" ::: "memory")
#define CP_WAIT0()  asm volatile("cp.async.wait_group 0;"  ::: "memory")

__device__ __forceinline__ void ldsm4(uint32_t* r, uint32_t addr) {
    asm volatile("ldmatrix.sync.aligned.m8n8.x4.shared.b16 {%0,%1,%2,%3}, [%4];"
                 : "=r"(r[0]), "=r"(r[1]), "=r"(r[2]), "=r"(r[3]) : "r"(addr));
}

__device__ __forceinline__ void mma16816(float* c, const uint32_t* a,
                                         uint32_t b0, uint32_t b1) {
    asm volatile(
        "mma.sync.aligned.m16n8k16.row.col.f32.f16.f16.f32 "
        "{%0,%1,%2,%3}, {%4,%5,%6,%7}, {%8,%9}, {%0,%1,%2,%3};"
        : "+f"(c[0]), "+f"(c[1]), "+f"(c[2]), "+f"(c[3])
        : "r"(a[0]), "r"(a[1]), "r"(a[2]), "r"(a[3]), "r"(b0), "r"(b1));
}

// ---------------------------------------------------------------------------
// fp32 -> fp16 hi/lo double-limb split of hidden_states
// ---------------------------------------------------------------------------
__global__ __launch_bounds__(256)
void convA_kernel(const float* __restrict__ A)
{
    size_t i = ((size_t)blockIdx.x * 256 + threadIdx.x) * 4;
    float4 v = *reinterpret_cast<const float4*>(A + i);
    __half h0 = __float2half(v.x), h1 = __float2half(v.y);
    __half h2 = __float2half(v.z), h3 = __float2half(v.w);
    __half l0 = __float2half(v.x - __half2float(h0));
    __half l1 = __float2half(v.y - __half2float(h1));
    __half l2 = __float2half(v.z - __half2float(h2));
    __half l3 = __float2half(v.w - __half2float(h3));
    __half2 a, b;
    a.x = h0; a.y = h1; b.x = h2; b.y = h3;
    *reinterpret_cast<__half2*>(&g_Ahi[i])     = a;
    *reinterpret_cast<__half2*>(&g_Ahi[i + 2]) = b;
    a.x = l0; a.y = l1; b.x = l2; b.y = l3;
    *reinterpret_cast<__half2*>(&g_Alo[i])     = a;
    *reinterpret_cast<__half2*>(&g_Alo[i + 2]) = b;
}

// ---------------------------------------------------------------------------
// w_qkv_a [K, N] -> transposed fp16 [N_PAD, K] (pad rows zeroed)
// ---------------------------------------------------------------------------
__global__ __launch_bounds__(256)
void convB_kernel(const float* __restrict__ W)
{
    __shared__ float t[32][33];
    const int kt = blockIdx.y * 32;
    const int nt = blockIdx.x * 32;
    const int tx = threadIdx.x, ty = threadIdx.y;

#pragma unroll
    for (int j = 0; j < 4; j++) {
        int k = kt + ty + j * 8;
        int n = nt + tx;
        t[ty + j * 8][tx] = (n < N_DIM) ? W[(size_t)k * N_DIM + n] : 0.f;
    }
    __syncthreads();
#pragma unroll
    for (int j = 0; j < 4; j++) {
        int n = nt + ty + j * 8;
        int k = kt + tx;
        g_Bhi[(size_t)n * K_DIM + k] = __float2half(t[tx][ty + j * 8]);
    }
}

// ---------------------------------------------------------------------------
// GEMM via mma.sync (HMMA): 256x128 block, 256 threads (8 warps, 4m x 2n),
// warp tile 64x64, fp16 2-product ((Ahi+Alo)*Bhi), 2-stage cp.async pipeline
// with a single __syncthreads per slab, 1 CTA/SM (full 255-reg budget so the
// 64x64 warp tile fits in registers -> 25% less smem fragment traffic).
//
// Stage layout (640 rows x 128B = 80KB):
//   rows   0-255 : Ahi  (offset 0)
//   rows 256-511 : Alo  (offset 32768)
//   rows 512-639 : Bhi  (offset 65536)
// Within a row, 16B chunk c stored at chunk (c ^ (row & 7)).
// ---------------------------------------------------------------------------
__global__ __launch_bounds__(256, 1)
void mma_gemm_kernel()
{
    extern __shared__ __align__(1024) char smem[];
    const uint32_t sbase = smem_u32(smem);
    const int tid  = threadIdx.x;
    const int bm   = blockIdx.y * MT;
    const int bn   = blockIdx.x * NT;
    const int lane = tid & 31;
    const int wid  = tid >> 5;           // 0..7
    const int wm   = wid & 3;            // m: 4 warps * 64
    const int wn   = wid >> 2;           // n: 2 warps * 64

    // ---- cooperative load: 20 x 16B per thread per stage ----
    const int rb    = tid >> 3;          // 0..31
    const int chunk = tid & 7;
    const uint32_t sw = (uint32_t)((chunk ^ (rb & 7)) << 4);
    const uint32_t dbase = sbase + (uint32_t)rb * 128 + sw;

    const char* pA = (const char*)(g_Ahi + (size_t)(bm + rb) * K_DIM) + chunk * 16;
    const char* pB = (const char*)(g_Bhi + (size_t)(bn + rb) * K_DIM) + chunk * 16;
    const ptrdiff_t dAlo = (const char*)g_Alo - (const char*)g_Ahi;
    const ptrdiff_t ROWB = (ptrdiff_t)32 * K_DIM * 2;   // 32 rows stride in bytes

    auto load_stage = [&](uint32_t soff, size_t koff) {
        uint32_t d = dbase + soff;
#pragma unroll
        for (int j = 0; j < 8; j++) {                   // A: 8 bands of 32 rows
            const char* s = pA + j * ROWB + koff;
            cpa16(d + (uint32_t)j * 4096,          s);          // Ahi
            cpa16(d + (uint32_t)j * 4096 + 32768,  s + dAlo);   // Alo
        }
#pragma unroll
        for (int j = 0; j < 4; j++) {                   // B: 4 bands of 32 rows
            cpa16(d + (uint32_t)j * 4096 + 65536, pB + j * ROWB + koff);
        }
    };

    // ---- ldmatrix address constants ----
    const int lr = lane & 15;
    const int lh = lane >> 4;
    const int l7 = lr & 7;
    uint32_t rowA[4], rowB[4];
#pragma unroll
    for (int mt = 0; mt < 4; mt++)
        rowA[mt] = (uint32_t)((wm * 64 + mt * 16 + lr) * 128);
#pragma unroll
    for (int p = 0; p < 4; p++)
        rowB[p] = (uint32_t)(65536 + (wn * 64 + p * 16 + lr) * 128);

    float acc[4][8][4];
#pragma unroll
    for (int mt = 0; mt < 4; mt++)
#pragma unroll
        for (int nt = 0; nt < 8; nt++)
#pragma unroll
            for (int r = 0; r < 4; r++) acc[mt][nt][r] = 0.f;

    // ---- prologue: slab 0 -> slot 0 ----
    load_stage(0, 0);
    CP_COMMIT();

    for (int s = 0; s < NSLAB; s++) {
        CP_WAIT0();              // all committed groups done -> slab s resident
        __syncthreads();         // data visible; slot (s+1)&1 free

        if (s + 1 < NSLAB)
            load_stage((uint32_t)((s + 1) & 1) * STAGE_BYTES,
                       (size_t)(s + 1) * 128);
        CP_COMMIT();             // in flight during compute below

        const uint32_t bs = sbase + (uint32_t)(s & 1) * STAGE_BYTES;
#pragma unroll
        for (int ks = 0; ks < 4; ks++) {
            const uint32_t swk = (uint32_t)(((2 * ks + lh) ^ l7) << 4);
            uint32_t aH[4][4], aL[4][4];
#pragma unroll
            for (int mt = 0; mt < 4; mt++) {
                ldsm4(aH[mt], bs + rowA[mt] + swk);
                ldsm4(aL[mt], bs + 32768 + rowA[mt] + swk);
            }
#pragma unroll
            for (int p = 0; p < 4; p++) {
                uint32_t bH[4];
                ldsm4(bH, bs + rowB[p] + swk);
#pragma unroll
                for (int mt = 0; mt < 4; mt++) {
#pragma unroll
                    for (int t = 0; t < 2; t++) {
                        float* c = acc[mt][2 * p + t];
                        mma16816(c, aH[mt], bH[t], bH[t + 2]);   // hi * bhi
                        mma16816(c, aL[mt], bH[t], bH[t + 2]);   // lo * bhi
                    }
                }
            }
        }
    }

    // ---- store accumulators to scratch ----
#pragma unroll
    for (int mt = 0; mt < 4; mt++) {
        const int row = bm + wm * 64 + mt * 16 + (lane >> 2);
#pragma unroll
        for (int nt = 0; nt < 8; nt++) {
            const int col = bn + wn * 64 + nt * 8 + (lane & 3) * 2;
            if (col < N_DIM) {
                float* p0 = &g_scratch[(size_t)row * N_DIM + col];
                float* p1 = &g_scratch[(size_t)(row + 8) * N_DIM + col];
                *reinterpret_cast<float2*>(p0) =
                    make_float2(acc[mt][nt][0], acc[mt][nt][1]);
                *reinterpret_cast<float2*>(p1) =
                    make_float2(acc[mt][nt][2], acc[mt][nt][3]);
            }
        }
    }
}

// ---------------------------------------------------------------------------
// Epilogue: one block per row. Dual RMSNorm + group amax quant + k_pe copy.
// ---------------------------------------------------------------------------
__global__ __launch_bounds__(256)
void epilogue_kernel(const float* __restrict__ wq,
                     const float* __restrict__ wkv,
                     float* __restrict__ out)
{
    const int m   = blockIdx.x;
    const int tid = threadIdx.x;
    const float* row = &g_scratch[(size_t)m * N_DIM];

    __shared__ float s_qn[Q_RANK];
    __shared__ float s_amax[N_GROUPS];
    __shared__ float s_red[16];
    __shared__ float s_rsq[2];

    if (tid < N_GROUPS) s_amax[tid] = 0.f;

    float qs = 0.f, kvs = 0.f;
    for (int i = tid; i < N_DIM / 4; i += 256) {
        float4 v = *reinterpret_cast<const float4*>(row + i * 4);
        int c = i * 4;
        float d = v.x * v.x + v.y * v.y + v.z * v.z + v.w * v.w;
        if (c < Q_RANK)                qs  += d;
        else if (c < Q_RANK + KV_RANK) kvs += d;
        else {
            *reinterpret_cast<float4*>(
                out + OUT_KPE + (size_t)m * ROPE_DIM + (c - Q_RANK - KV_RANK)) = v;
        }
    }
#pragma unroll
    for (int o = 16; o > 0; o >>= 1) {
        qs  += __shfl_down_sync(0xFFFFFFFFu, qs,  o);
        kvs += __shfl_down_sync(0xFFFFFFFFu, kvs, o);
    }
    int wid = tid >> 5, lane = tid & 31;
    if (lane == 0) { s_red[wid] = qs; s_red[8 + wid] = kvs; }
    __syncthreads();
    if (tid == 0) {
        float a = 0.f, b = 0.f;
#pragma unroll
        for (int w = 0; w < 8; w++) { a += s_red[w]; b += s_red[8 + w]; }
        s_rsq[0] = rsqrtf(a / (float)Q_RANK  + EPS_RMS);
        s_rsq[1] = rsqrtf(b / (float)KV_RANK + EPS_RMS);
    }
    __syncthreads();
    const float rq = s_rsq[0], rkv = s_rsq[1];

    for (int i = tid; i < Q_RANK / 4; i += 256) {
        int c = i * 4;
        float4 v = *reinterpret_cast<const float4*>(row + c);
        float4 w = *reinterpret_cast<const float4*>(wq + c);
        float4 q;
        q.x = v.x * rq * w.x;  q.y = v.y * rq * w.y;
        q.z = v.z * rq * w.z;  q.w = v.w * rq * w.w;
        *reinterpret_cast<float4*>(&s_qn[c]) = q;
        float am = fmaxf(fmaxf(fabsf(q.x), fabsf(q.y)),
                         fmaxf(fabsf(q.z), fabsf(q.w)));
        atomicMax(reinterpret_cast<int*>(&s_amax[c >> 7]), __float_as_int(am));
    }
    for (int i = tid; i < KV_RANK / 4; i += 256) {
        int c = i * 4;
        float4 v = *reinterpret_cast<const float4*>(row + Q_RANK + c);
        float4 w = *reinterpret_cast<const float4*>(wkv + c);
        float4 o;
        o.x = v.x * rkv * w.x;  o.y = v.y * rkv * w.y;
        o.z = v.z * rkv * w.z;  o.w = v.w * rkv * w.w;
        *reinterpret_cast<float4*>(out + OUT_KV + (size_t)m * KV_RANK + c) = o;
    }
    __syncthreads();

    if (tid < N_GROUPS) {
        float sc = fmaxf(s_amax[tid] / FP8_MAX, 1e-12f);
        s_amax[tid] = sc;
        out[OUT_SC + (size_t)m * N_GROUPS + tid] = sc;
    }
    __syncthreads();

    for (int i = tid; i < Q_RANK / 4; i += 256) {
        int c = i * 4;
        float inv = 1.0f / s_amax[c >> 7];
        float4 q = *reinterpret_cast<const float4*>(&s_qn[c]);
        float4 o;
        o.x = q.x * inv; o.y = q.y * inv; o.z = q.z * inv; o.w = q.w * inv;
        *reinterpret_cast<float4*>(out + OUT_QQ + (size_t)m * Q_RANK + c) = o;
    }
}

// ---------------------------------------------------------------------------
extern "C" void kernel_launch(void* const* d_in, const int* in_sizes, int n_in,
                              void* d_out, int out_size)
{
    const float* hidden = (const float*)d_in[0];   // [8192, 7168]
    const float* w_qkv  = (const float*)d_in[1];   // [7168, 2112]
    const float* wq     = (const float*)d_in[2];   // [1536]
    const float* wkv    = (const float*)d_in[3];   // [512]
    float* out = (float*)d_out;

    static bool attr_set = false;
    if (!attr_set) {
        cudaFuncSetAttribute(mma_gemm_kernel,
                             cudaFuncAttributeMaxDynamicSharedMemorySize, SMEM_TOTAL);
        attr_set = true;
    }

    convA_kernel<<<(M_DIM * K_DIM) / (256 * 4), 256>>>(hidden);
    convB_kernel<<<dim3(N_PAD / 32, K_DIM / 32), dim3(32, 8)>>>(w_qkv);
    mma_gemm_kernel<<<dim3(N_PAD / NT, M_DIM / MT), 256, SMEM_TOTAL>>>();
    epilogue_kernel<<<M_DIM, 256>>>(wq, wkv, out);
}

// round 11
// speedup vs baseline: 1.0367x; 1.0367x over previous
#include <cuda_runtime.h>
#include <cuda_fp16.h>
#include <cstdint>
#include <cstddef>

// ---------------- problem constants ----------------
#define M_DIM 8192
#define K_DIM 7168
#define N_DIM 2112           // 1536 + 512 + 64
#define Q_RANK 1536
#define KV_RANK 512
#define ROPE_DIM 64
#define N_GROUPS 12
#define FP8_MAX 448.0f
#define EPS_RMS 1e-6f

#define OUT_QQ   ((size_t)0)
#define OUT_SC   ((size_t)M_DIM * Q_RANK)
#define OUT_KV   (OUT_SC + (size_t)M_DIM * N_GROUPS)
#define OUT_KPE  (OUT_KV + (size_t)M_DIM * KV_RANK)

// ---------------- GEMM tiling ----------------
#define MT 128
#define NT 128
#define KB 64                        // fp16 elems per K slab (128 bytes per row)
#define NSLAB (K_DIM / KB)           // 112
#define N_PAD 2176                   // 17 * 128
#define STAGE_BYTES (48 * 1024)      // Ahi 16K | Alo 16K | Bhi 16K
#define NSTAGE 2
#define SMEM_TOTAL (NSTAGE * STAGE_BYTES)   // 96 KB -> 2 CTAs/SM

// ---------------- device scratch (no cudaMalloc allowed) ----------------
__device__ __align__(1024) __half g_Ahi[(size_t)M_DIM * K_DIM];
__device__ __align__(1024) __half g_Alo[(size_t)M_DIM * K_DIM];
__device__ __align__(1024) __half g_Bhi[(size_t)N_PAD * K_DIM];   // [n][k] transposed
__device__ __align__(16)   float  g_scratch[(size_t)M_DIM * N_DIM];

// ---------------- PTX helpers (baseline PTX only: sm_80-era) ----------------
__device__ __forceinline__ uint32_t smem_u32(const void* p) {
    uint32_t a;
    asm("{ .reg .u64 t; cvta.to.shared.u64 t, %1; cvt.u32.u64 %0, t; }" : "=r"(a) : "l"(p));
    return a;
}

__device__ __forceinline__ void cpa16(uint32_t dst, const void* src) {
    asm volatile("cp.async.cg.shared.global [%0], [%1], 16;" :: "r"(dst), "l"(src));
}
#define CP_COMMIT() asm volatile("cp.async.commit_group;" ::: "memory")
#define CP_WAIT0()  asm volatile("cp.async.wait_group 0;"  ::: "memory")

__device__ __forceinline__ void ldsm4(uint32_t* r, uint32_t addr) {
    asm volatile("ldmatrix.sync.aligned.m8n8.x4.shared.b16 {%0,%1,%2,%3}, [%4];"
                 : "=r"(r[0]), "=r"(r[1]), "=r"(r[2]), "=r"(r[3]) : "r"(addr));
}

__device__ __forceinline__ void mma16816(float* c, const uint32_t* a,
                                         uint32_t b0, uint32_t b1) {
    asm volatile(
        "mma.sync.aligned.m16n8k16.row.col.f32.f16.f16.f32 "
        "{%0,%1,%2,%3}, {%4,%5,%6,%7}, {%8,%9}, {%0,%1,%2,%3};"
        : "+f"(c[0]), "+f"(c[1]), "+f"(c[2]), "+f"(c[3])
        : "r"(a[0]), "r"(a[1]), "r"(a[2]), "r"(a[3]), "r"(b0), "r"(b1));
}

// ---------------------------------------------------------------------------
// fp32 -> fp16 hi/lo double-limb split of hidden_states
// ---------------------------------------------------------------------------
__global__ __launch_bounds__(256)
void convA_kernel(const float* __restrict__ A)
{
    size_t i = ((size_t)blockIdx.x * 256 + threadIdx.x) * 4;
    float4 v = *reinterpret_cast<const float4*>(A + i);
    __half h0 = __float2half(v.x), h1 = __float2half(v.y);
    __half h2 = __float2half(v.z), h3 = __float2half(v.w);
    __half l0 = __float2half(v.x - __half2float(h0));
    __half l1 = __float2half(v.y - __half2float(h1));
    __half l2 = __float2half(v.z - __half2float(h2));
    __half l3 = __float2half(v.w - __half2float(h3));
    __half2 a, b;
    a.x = h0; a.y = h1; b.x = h2; b.y = h3;
    *reinterpret_cast<__half2*>(&g_Ahi[i])     = a;
    *reinterpret_cast<__half2*>(&g_Ahi[i + 2]) = b;
    a.x = l0; a.y = l1; b.x = l2; b.y = l3;
    *reinterpret_cast<__half2*>(&g_Alo[i])     = a;
    *reinterpret_cast<__half2*>(&g_Alo[i + 2]) = b;
}

// ---------------------------------------------------------------------------
// w_qkv_a [K, N] -> transposed fp16 [N_PAD, K] (pad rows zeroed)
// ---------------------------------------------------------------------------
__global__ __launch_bounds__(256)
void convB_kernel(const float* __restrict__ W)
{
    __shared__ float t[32][33];
    const int kt = blockIdx.y * 32;
    const int nt = blockIdx.x * 32;
    const int tx = threadIdx.x, ty = threadIdx.y;

#pragma unroll
    for (int j = 0; j < 4; j++) {
        int k = kt + ty + j * 8;
        int n = nt + tx;
        t[ty + j * 8][tx] = (n < N_DIM) ? W[(size_t)k * N_DIM + n] : 0.f;
    }
    __syncthreads();
#pragma unroll
    for (int j = 0; j < 4; j++) {
        int n = nt + ty + j * 8;
        int k = kt + tx;
        g_Bhi[(size_t)n * K_DIM + k] = __float2half(t[tx][ty + j * 8]);
    }
}

// ---------------------------------------------------------------------------
// GEMM via mma.sync (HMMA): 128x128 block, 256 threads (8 warps, 4m x 2n),
// warp tile 32x64, fp16 2-product ((Ahi+Alo)*Bhi), 2-stage cp.async pipeline,
// single __syncthreads per slab, 2 CTAs per SM.
//
// This round: MMAs issued in TWO PASSES (all hi-products, then all
// lo-products) so each accumulator's two writes are 16 MMAs apart instead
// of back-to-back -- breaks the HMMA RAW dependency chains.
//
// Stage layout (384 rows x 128B = 48KB):
//   rows   0-127 : Ahi  (offset 0)
//   rows 128-255 : Alo  (offset 16384)
//   rows 256-383 : Bhi  (offset 32768)
// Within a row, 16B chunk c stored at chunk (c ^ (row & 7)).
// ---------------------------------------------------------------------------
__global__ __launch_bounds__(256, 2)
void mma_gemm_kernel()
{
    extern __shared__ __align__(1024) char smem[];
    const uint32_t sbase = smem_u32(smem);
    const int tid  = threadIdx.x;
    const int bm   = blockIdx.y * MT;
    const int bn   = blockIdx.x * NT;
    const int lane = tid & 31;
    const int wid  = tid >> 5;           // 0..7
    const int wm   = wid & 3;            // m: 4 warps * 32
    const int wn   = wid >> 2;           // n: 2 warps * 64

    // ---- cooperative load: 12 x 16B per thread per stage ----
    const int rb    = tid >> 3;          // 0..31
    const int chunk = tid & 7;
    const uint32_t sw = (uint32_t)((chunk ^ (rb & 7)) << 4);
    const uint32_t dbase = sbase + (uint32_t)rb * 128 + sw;

    const char* pAh[4]; const char* pBh[4];
#pragma unroll
    for (int j = 0; j < 4; j++) {
        pAh[j] = (const char*)(g_Ahi + (size_t)(bm + j * 32 + rb) * K_DIM) + chunk * 16;
        pBh[j] = (const char*)(g_Bhi + (size_t)(bn + j * 32 + rb) * K_DIM) + chunk * 16;
    }
    const ptrdiff_t dAlo = (const char*)g_Alo - (const char*)g_Ahi;

    auto load_stage = [&](uint32_t soff, size_t koff) {
        uint32_t d = dbase + soff;
#pragma unroll
        for (int j = 0; j < 4; j++) {
            uint32_t dj = d + (uint32_t)j * 4096;
            cpa16(dj,          pAh[j] + koff);          // Ahi
            cpa16(dj + 16384,  pAh[j] + koff + dAlo);   // Alo
            cpa16(dj + 32768,  pBh[j] + koff);          // Bhi
        }
    };

    // ---- ldmatrix address constants ----
    const int lr = lane & 15;
    const int lh = lane >> 4;
    const int l7 = lr & 7;
    uint32_t rowA[2], rowB[4];
#pragma unroll
    for (int mt = 0; mt < 2; mt++)
        rowA[mt] = (uint32_t)((wm * 32 + mt * 16 + lr) * 128);
#pragma unroll
    for (int p = 0; p < 4; p++)
        rowB[p] = (uint32_t)(32768 + (wn * 64 + p * 16 + lr) * 128);

    float acc[2][8][4];
#pragma unroll
    for (int mt = 0; mt < 2; mt++)
#pragma unroll
        for (int nt = 0; nt < 8; nt++)
#pragma unroll
            for (int r = 0; r < 4; r++) acc[mt][nt][r] = 0.f;

    // ---- prologue: slab 0 -> slot 0 ----
    load_stage(0, 0);
    CP_COMMIT();

    for (int s = 0; s < NSLAB; s++) {
        CP_WAIT0();              // all committed groups done -> slab s resident
        __syncthreads();         // data visible; slot (s+1)&1 free

        if (s + 1 < NSLAB)
            load_stage((uint32_t)((s + 1) & 1) * STAGE_BYTES,
                       (size_t)(s + 1) * 128);
        CP_COMMIT();             // in flight during compute below

        const uint32_t bs = sbase + (uint32_t)(s & 1) * STAGE_BYTES;
#pragma unroll
        for (int ks = 0; ks < 4; ks++) {
            const uint32_t swk = (uint32_t)(((2 * ks + lh) ^ l7) << 4);
            // All 12 LDSMs for this ks issued back-to-back.
            uint32_t aH[2][4], aL[2][4], bH[4][4];
#pragma unroll
            for (int mt = 0; mt < 2; mt++) {
                ldsm4(aH[mt], bs + rowA[mt] + swk);
                ldsm4(aL[mt], bs + 16384 + rowA[mt] + swk);
            }
#pragma unroll
            for (int p = 0; p < 4; p++)
                ldsm4(bH[p], bs + rowB[p] + swk);

            // Pass 1: all 16 hi-products (each acc touched once).
#pragma unroll
            for (int p = 0; p < 4; p++)
#pragma unroll
                for (int mt = 0; mt < 2; mt++)
#pragma unroll
                    for (int t = 0; t < 2; t++)
                        mma16816(acc[mt][2 * p + t], aH[mt],
                                 bH[p][t], bH[p][t + 2]);

            // Pass 2: all 16 lo-products (acc reuse distance = 16 MMAs).
#pragma unroll
            for (int p = 0; p < 4; p++)
#pragma unroll
                for (int mt = 0; mt < 2; mt++)
#pragma unroll
                    for (int t = 0; t < 2; t++)
                        mma16816(acc[mt][2 * p + t], aL[mt],
                                 bH[p][t], bH[p][t + 2]);
        }
    }

    // ---- store accumulators to scratch ----
#pragma unroll
    for (int mt = 0; mt < 2; mt++) {
        const int row = bm + wm * 32 + mt * 16 + (lane >> 2);
#pragma unroll
        for (int nt = 0; nt < 8; nt++) {
            const int col = bn + wn * 64 + nt * 8 + (lane & 3) * 2;
            if (col < N_DIM) {
                float* p0 = &g_scratch[(size_t)row * N_DIM + col];
                float* p1 = &g_scratch[(size_t)(row + 8) * N_DIM + col];
                *reinterpret_cast<float2*>(p0) =
                    make_float2(acc[mt][nt][0], acc[mt][nt][1]);
                *reinterpret_cast<float2*>(p1) =
                    make_float2(acc[mt][nt][2], acc[mt][nt][3]);
            }
        }
    }
}

// ---------------------------------------------------------------------------
// Epilogue: one block per row. Dual RMSNorm + group amax quant + k_pe copy.
// ---------------------------------------------------------------------------
__global__ __launch_bounds__(256)
void epilogue_kernel(const float* __restrict__ wq,
                     const float* __restrict__ wkv,
                     float* __restrict__ out)
{
    const int m   = blockIdx.x;
    const int tid = threadIdx.x;
    const float* row = &g_scratch[(size_t)m * N_DIM];

    __shared__ float s_qn[Q_RANK];
    __shared__ float s_amax[N_GROUPS];
    __shared__ float s_red[16];
    __shared__ float s_rsq[2];

    if (tid < N_GROUPS) s_amax[tid] = 0.f;

    float qs = 0.f, kvs = 0.f;
    for (int i = tid; i < N_DIM / 4; i += 256) {
        float4 v = *reinterpret_cast<const float4*>(row + i * 4);
        int c = i * 4;
        float d = v.x * v.x + v.y * v.y + v.z * v.z + v.w * v.w;
        if (c < Q_RANK)                qs  += d;
        else if (c < Q_RANK + KV_RANK) kvs += d;
        else {
            *reinterpret_cast<float4*>(
                out + OUT_KPE + (size_t)m * ROPE_DIM + (c - Q_RANK - KV_RANK)) = v;
        }
    }
#pragma unroll
    for (int o = 16; o > 0; o >>= 1) {
        qs  += __shfl_down_sync(0xFFFFFFFFu, qs,  o);
        kvs += __shfl_down_sync(0xFFFFFFFFu, kvs, o);
    }
    int wid = tid >> 5, lane = tid & 31;
    if (lane == 0) { s_red[wid] = qs; s_red[8 + wid] = kvs; }
    __syncthreads();
    if (tid == 0) {
        float a = 0.f, b = 0.f;
#pragma unroll
        for (int w = 0; w < 8; w++) { a += s_red[w]; b += s_red[8 + w]; }
        s_rsq[0] = rsqrtf(a / (float)Q_RANK  + EPS_RMS);
        s_rsq[1] = rsqrtf(b / (float)KV_RANK + EPS_RMS);
    }
    __syncthreads();
    const float rq = s_rsq[0], rkv = s_rsq[1];

    for (int i = tid; i < Q_RANK / 4; i += 256) {
        int c = i * 4;
        float4 v = *reinterpret_cast<const float4*>(row + c);
        float4 w = *reinterpret_cast<const float4*>(wq + c);
        float4 q;
        q.x = v.x * rq * w.x;  q.y = v.y * rq * w.y;
        q.z = v.z * rq * w.z;  q.w = v.w * rq * w.w;
        *reinterpret_cast<float4*>(&s_qn[c]) = q;
        float am = fmaxf(fmaxf(fabsf(q.x), fabsf(q.y)),
                         fmaxf(fabsf(q.z), fabsf(q.w)));
        atomicMax(reinterpret_cast<int*>(&s_amax[c >> 7]), __float_as_int(am));
    }
    for (int i = tid; i < KV_RANK / 4; i += 256) {
        int c = i * 4;
        float4 v = *reinterpret_cast<const float4*>(row + Q_RANK + c);
        float4 w = *reinterpret_cast<const float4*>(wkv + c);
        float4 o;
        o.x = v.x * rkv * w.x;  o.y = v.y * rkv * w.y;
        o.z = v.z * rkv * w.z;  o.w = v.w * rkv * w.w;
        *reinterpret_cast<float4*>(out + OUT_KV + (size_t)m * KV_RANK + c) = o;
    }
    __syncthreads();

    if (tid < N_GROUPS) {
        float sc = fmaxf(s_amax[tid] / FP8_MAX, 1e-12f);
        s_amax[tid] = sc;
        out[OUT_SC + (size_t)m * N_GROUPS + tid] = sc;
    }
    __syncthreads();

    for (int i = tid; i < Q_RANK / 4; i += 256) {
        int c = i * 4;
        float inv = 1.0f / s_amax[c >> 7];
        float4 q = *reinterpret_cast<const float4*>(&s_qn[c]);
        float4 o;
        o.x = q.x * inv; o.y = q.y * inv; o.z = q.z * inv; o.w = q.w * inv;
        *reinterpret_cast<float4*>(out + OUT_QQ + (size_t)m * Q_RANK + c) = o;
    }
}

// ---------------------------------------------------------------------------
extern "C" void kernel_launch(void* const* d_in, const int* in_sizes, int n_in,
                              void* d_out, int out_size)
{
    const float* hidden = (const float*)d_in[0];   // [8192, 7168]
    const float* w_qkv  = (const float*)d_in[1];   // [7168, 2112]
    const float* wq     = (const float*)d_in[2];   // [1536]
    const float* wkv    = (const float*)d_in[3];   // [512]
    float* out = (float*)d_out;

    static bool attr_set = false;
    if (!attr_set) {
        cudaFuncSetAttribute(mma_gemm_kernel,
                             cudaFuncAttributeMaxDynamicSharedMemorySize, SMEM_TOTAL);
        attr_set = true;
    }

    convA_kernel<<<(M_DIM * K_DIM) / (256 * 4), 256>>>(hidden);
    convB_kernel<<<dim3(N_PAD / 32, K_DIM / 32), dim3(32, 8)>>>(w_qkv);
    mma_gemm_kernel<<<dim3(N_PAD / NT, M_DIM / MT), 256, SMEM_TOTAL>>>();
    epilogue_kernel<<<M_DIM, 256>>>(wq, wkv, out);
}

// round 12
// speedup vs baseline: 1.0936x; 1.0549x over previous
#include <cuda_runtime.h>
#include <cuda_fp16.h>
#include <cstdint>
#include <cstddef>

// ---------------- problem constants ----------------
#define M_DIM 8192
#define K_DIM 7168
#define N_DIM 2112           // 1536 + 512 + 64
#define Q_RANK 1536
#define KV_RANK 512
#define ROPE_DIM 64
#define N_GROUPS 12
#define FP8_MAX 448.0f
#define EPS_RMS 1e-6f

#define OUT_QQ   ((size_t)0)
#define OUT_SC   ((size_t)M_DIM * Q_RANK)
#define OUT_KV   (OUT_SC + (size_t)M_DIM * N_GROUPS)
#define OUT_KPE  (OUT_KV + (size_t)M_DIM * KV_RANK)

// ---------------- GEMM tiling ----------------
#define MT 128
#define NT 128
#define KB 64                        // fp16 elems per K slab (128 bytes per row)
#define NSLAB (K_DIM / KB)           // 112
#define N_PAD 2176                   // 17 * 128
#define STAGE_BYTES (48 * 1024)      // Ahi 16K | Alo 16K | Bhi 16K
#define NSTAGE 2
#define SMEM_TOTAL (NSTAGE * STAGE_BYTES)   // 96 KB -> 2 CTAs/SM

// fused conv grid split
#define NBLK_A ((M_DIM * (size_t)K_DIM) / (256 * 4))   // 57344
#define NBLK_B_X (N_PAD / 32)                           // 68
#define NBLK_B   (NBLK_B_X * (K_DIM / 32))              // 15232

// ---------------- device scratch (no cudaMalloc allowed) ----------------
__device__ __align__(1024) __half g_Ahi[(size_t)M_DIM * K_DIM];
__device__ __align__(1024) __half g_Alo[(size_t)M_DIM * K_DIM];
__device__ __align__(1024) __half g_Bhi[(size_t)N_PAD * K_DIM];   // [n][k] transposed
__device__ __align__(16)   float  g_scratch[(size_t)M_DIM * N_DIM];

// ---------------- PTX helpers (baseline PTX only: sm_80-era) ----------------
__device__ __forceinline__ uint32_t smem_u32(const void* p) {
    uint32_t a;
    asm("{ .reg .u64 t; cvta.to.shared.u64 t, %1; cvt.u32.u64 %0, t; }" : "=r"(a) : "l"(p));
    return a;
}

__device__ __forceinline__ void cpa16(uint32_t dst, const void* src) {
    asm volatile("cp.async.cg.shared.global [%0], [%1], 16;" :: "r"(dst), "l"(src));
}
#define CP_COMMIT() asm volatile("cp.async.commit_group;" ::: "memory")
#define CP_WAIT0()  asm volatile("cp.async.wait_group 0;"  ::: "memory")

__device__ __forceinline__ void ldsm4(uint32_t* r, uint32_t addr) {
    asm volatile("ldmatrix.sync.aligned.m8n8.x4.shared.b16 {%0,%1,%2,%3}, [%4];"
                 : "=r"(r[0]), "=r"(r[1]), "=r"(r[2]), "=r"(r[3]) : "r"(addr));
}

__device__ __forceinline__ void mma16816(float* c, const uint32_t* a,
                                         uint32_t b0, uint32_t b1) {
    asm volatile(
        "mma.sync.aligned.m16n8k16.row.col.f32.f16.f16.f32 "
        "{%0,%1,%2,%3}, {%4,%5,%6,%7}, {%8,%9}, {%0,%1,%2,%3};"
        : "+f"(c[0]), "+f"(c[1]), "+f"(c[2]), "+f"(c[3])
        : "r"(a[0]), "r"(a[1]), "r"(a[2]), "r"(a[3]), "r"(b0), "r"(b1));
}

// ---------------------------------------------------------------------------
// Fused conversion kernel: blocks [0, NBLK_A) do the fp32 -> fp16 hi/lo split
// of hidden_states; blocks [NBLK_A, NBLK_A+NBLK_B) transpose w_qkv_a into
// fp16 [N_PAD, K]. One launch so both phases share the SM pool.
// ---------------------------------------------------------------------------
__global__ __launch_bounds__(256)
void conv_fused_kernel(const float* __restrict__ A, const float* __restrict__ W)
{
    __shared__ float t[32][33];
    const int tid = threadIdx.x;

    if (blockIdx.x < (unsigned)NBLK_A) {
        // ---- convA: hi/lo double-limb split ----
        size_t i = ((size_t)blockIdx.x * 256 + tid) * 4;
        float4 v = *reinterpret_cast<const float4*>(A + i);
        __half h0 = __float2half(v.x), h1 = __float2half(v.y);
        __half h2 = __float2half(v.z), h3 = __float2half(v.w);
        __half l0 = __float2half(v.x - __half2float(h0));
        __half l1 = __float2half(v.y - __half2float(h1));
        __half l2 = __float2half(v.z - __half2float(h2));
        __half l3 = __float2half(v.w - __half2float(h3));
        __half2 a, b;
        a.x = h0; a.y = h1; b.x = h2; b.y = h3;
        *reinterpret_cast<__half2*>(&g_Ahi[i])     = a;
        *reinterpret_cast<__half2*>(&g_Ahi[i + 2]) = b;
        a.x = l0; a.y = l1; b.x = l2; b.y = l3;
        *reinterpret_cast<__half2*>(&g_Alo[i])     = a;
        *reinterpret_cast<__half2*>(&g_Alo[i + 2]) = b;
    } else {
        // ---- convB: transpose + fp16 convert ----
        const int bid = (int)blockIdx.x - (int)NBLK_A;
        const int nt  = (bid % NBLK_B_X) * 32;
        const int kt  = (bid / NBLK_B_X) * 32;
        const int tx = tid & 31, ty = tid >> 5;

#pragma unroll
        for (int j = 0; j < 4; j++) {
            int k = kt + ty + j * 8;
            int n = nt + tx;
            t[ty + j * 8][tx] = (n < N_DIM) ? W[(size_t)k * N_DIM + n] : 0.f;
        }
        __syncthreads();
#pragma unroll
        for (int j = 0; j < 4; j++) {
            int n = nt + ty + j * 8;
            int k = kt + tx;
            g_Bhi[(size_t)n * K_DIM + k] = __float2half(t[tx][ty + j * 8]);
        }
    }
}

// ---------------------------------------------------------------------------
// GEMM via mma.sync (HMMA): 128x128 block, 256 threads (8 warps, 4m x 2n),
// warp tile 32x64, fp16 2-product ((Ahi+Alo)*Bhi), 2-stage cp.async pipeline,
// single __syncthreads per slab, 2 CTAs per SM.
//
// Tail-tile optimization: the last N tile (bn=2048) has only 64 valid cols;
// its wn=1 warps skip all LDSM/MMA work and its out-of-range B cp.asyncs are
// skipped (those smem rows are never read).
//
// Stage layout (384 rows x 128B = 48KB):
//   rows   0-127 : Ahi  (offset 0)
//   rows 128-255 : Alo  (offset 16384)
//   rows 256-383 : Bhi  (offset 32768)
// Within a row, 16B chunk c stored at chunk (c ^ (row & 7)).
// ---------------------------------------------------------------------------
__global__ __launch_bounds__(256, 2)
void mma_gemm_kernel()
{
    extern __shared__ __align__(1024) char smem[];
    const uint32_t sbase = smem_u32(smem);
    const int tid  = threadIdx.x;
    const int bm   = blockIdx.y * MT;
    const int bn   = blockIdx.x * NT;
    const int lane = tid & 31;
    const int wid  = tid >> 5;           // 0..7
    const int wm   = wid & 3;            // m: 4 warps * 32
    const int wn   = wid >> 2;           // n: 2 warps * 64

    // This warp produces valid output only if its 64-col band intersects N.
    const bool active = (bn + wn * 64) < N_DIM;

    // ---- cooperative load: up to 12 x 16B per thread per stage ----
    const int rb    = tid >> 3;          // 0..31
    const int chunk = tid & 7;
    const uint32_t sw = (uint32_t)((chunk ^ (rb & 7)) << 4);
    const uint32_t dbase = sbase + (uint32_t)rb * 128 + sw;

    const char* pAh[4]; const char* pBh[4];
    bool loadB[4];
#pragma unroll
    for (int j = 0; j < 4; j++) {
        pAh[j] = (const char*)(g_Ahi + (size_t)(bm + j * 32 + rb) * K_DIM) + chunk * 16;
        pBh[j] = (const char*)(g_Bhi + (size_t)(bn + j * 32 + rb) * K_DIM) + chunk * 16;
        loadB[j] = (bn + j * 32) < N_DIM;    // skip padded B bands (tail tile)
    }
    const ptrdiff_t dAlo = (const char*)g_Alo - (const char*)g_Ahi;

    auto load_stage = [&](uint32_t soff, size_t koff) {
        uint32_t d = dbase + soff;
#pragma unroll
        for (int j = 0; j < 4; j++) {
            uint32_t dj = d + (uint32_t)j * 4096;
            cpa16(dj,          pAh[j] + koff);          // Ahi
            cpa16(dj + 16384,  pAh[j] + koff + dAlo);   // Alo
            if (loadB[j]) cpa16(dj + 32768, pBh[j] + koff);   // Bhi
        }
    };

    // ---- ldmatrix address constants ----
    const int lr = lane & 15;
    const int lh = lane >> 4;
    const int l7 = lr & 7;
    uint32_t rowA[2], rowB[4];
#pragma unroll
    for (int mt = 0; mt < 2; mt++)
        rowA[mt] = (uint32_t)((wm * 32 + mt * 16 + lr) * 128);
#pragma unroll
    for (int p = 0; p < 4; p++)
        rowB[p] = (uint32_t)(32768 + (wn * 64 + p * 16 + lr) * 128);

    float acc[2][8][4];
#pragma unroll
    for (int mt = 0; mt < 2; mt++)
#pragma unroll
        for (int nt = 0; nt < 8; nt++)
#pragma unroll
            for (int r = 0; r < 4; r++) acc[mt][nt][r] = 0.f;

    // ---- prologue: slab 0 -> slot 0 ----
    load_stage(0, 0);
    CP_COMMIT();

    for (int s = 0; s < NSLAB; s++) {
        CP_WAIT0();              // all committed groups done -> slab s resident
        __syncthreads();         // data visible; slot (s+1)&1 free

        if (s + 1 < NSLAB)
            load_stage((uint32_t)((s + 1) & 1) * STAGE_BYTES,
                       (size_t)(s + 1) * 128);
        CP_COMMIT();             // in flight during compute below

        if (active) {
            const uint32_t bs = sbase + (uint32_t)(s & 1) * STAGE_BYTES;
#pragma unroll
            for (int ks = 0; ks < 4; ks++) {
                const uint32_t swk = (uint32_t)(((2 * ks + lh) ^ l7) << 4);
                uint32_t aH[2][4], aL[2][4];
#pragma unroll
                for (int mt = 0; mt < 2; mt++) {
                    ldsm4(aH[mt], bs + rowA[mt] + swk);
                    ldsm4(aL[mt], bs + 16384 + rowA[mt] + swk);
                }
#pragma unroll
                for (int p = 0; p < 4; p++) {
                    uint32_t bH[4];
                    ldsm4(bH, bs + rowB[p] + swk);
#pragma unroll
                    for (int mt = 0; mt < 2; mt++) {
#pragma unroll
                        for (int t = 0; t < 2; t++) {
                            float* c = acc[mt][2 * p + t];
                            mma16816(c, aH[mt], bH[t], bH[t + 2]);   // hi * bhi
                            mma16816(c, aL[mt], bH[t], bH[t + 2]);   // lo * bhi
                        }
                    }
                }
            }
        }
    }

    // ---- store accumulators to scratch ----
    if (active) {
#pragma unroll
        for (int mt = 0; mt < 2; mt++) {
            const int row = bm + wm * 32 + mt * 16 + (lane >> 2);
#pragma unroll
            for (int nt = 0; nt < 8; nt++) {
                const int col = bn + wn * 64 + nt * 8 + (lane & 3) * 2;
                if (col < N_DIM) {
                    float* p0 = &g_scratch[(size_t)row * N_DIM + col];
                    float* p1 = &g_scratch[(size_t)(row + 8) * N_DIM + col];
                    *reinterpret_cast<float2*>(p0) =
                        make_float2(acc[mt][nt][0], acc[mt][nt][1]);
                    *reinterpret_cast<float2*>(p1) =
                        make_float2(acc[mt][nt][2], acc[mt][nt][3]);
                }
            }
        }
    }
}

// ---------------------------------------------------------------------------
// Epilogue: one block per row. Dual RMSNorm + group amax quant + k_pe copy.
// ---------------------------------------------------------------------------
__global__ __launch_bounds__(256)
void epilogue_kernel(const float* __restrict__ wq,
                     const float* __restrict__ wkv,
                     float* __restrict__ out)
{
    const int m   = blockIdx.x;
    const int tid = threadIdx.x;
    const float* row = &g_scratch[(size_t)m * N_DIM];

    __shared__ float s_qn[Q_RANK];
    __shared__ float s_amax[N_GROUPS];
    __shared__ float s_red[16];
    __shared__ float s_rsq[2];

    if (tid < N_GROUPS) s_amax[tid] = 0.f;

    float qs = 0.f, kvs = 0.f;
    for (int i = tid; i < N_DIM / 4; i += 256) {
        float4 v = *reinterpret_cast<const float4*>(row + i * 4);
        int c = i * 4;
        float d = v.x * v.x + v.y * v.y + v.z * v.z + v.w * v.w;
        if (c < Q_RANK)                qs  += d;
        else if (c < Q_RANK + KV_RANK) kvs += d;
        else {
            *reinterpret_cast<float4*>(
                out + OUT_KPE + (size_t)m * ROPE_DIM + (c - Q_RANK - KV_RANK)) = v;
        }
    }
#pragma unroll
    for (int o = 16; o > 0; o >>= 1) {
        qs  += __shfl_down_sync(0xFFFFFFFFu, qs,  o);
        kvs += __shfl_down_sync(0xFFFFFFFFu, kvs, o);
    }
    int wid = tid >> 5, lane = tid & 31;
    if (lane == 0) { s_red[wid] = qs; s_red[8 + wid] = kvs; }
    __syncthreads();
    if (tid == 0) {
        float a = 0.f, b = 0.f;
#pragma unroll
        for (int w = 0; w < 8; w++) { a += s_red[w]; b += s_red[8 + w]; }
        s_rsq[0] = rsqrtf(a / (float)Q_RANK  + EPS_RMS);
        s_rsq[1] = rsqrtf(b / (float)KV_RANK + EPS_RMS);
    }
    __syncthreads();
    const float rq = s_rsq[0], rkv = s_rsq[1];

    for (int i = tid; i < Q_RANK / 4; i += 256) {
        int c = i * 4;
        float4 v = *reinterpret_cast<const float4*>(row + c);
        float4 w = *reinterpret_cast<const float4*>(wq + c);
        float4 q;
        q.x = v.x * rq * w.x;  q.y = v.y * rq * w.y;
        q.z = v.z * rq * w.z;  q.w = v.w * rq * w.w;
        *reinterpret_cast<float4*>(&s_qn[c]) = q;
        float am = fmaxf(fmaxf(fabsf(q.x), fabsf(q.y)),
                         fmaxf(fabsf(q.z), fabsf(q.w)));
        atomicMax(reinterpret_cast<int*>(&s_amax[c >> 7]), __float_as_int(am));
    }
    for (int i = tid; i < KV_RANK / 4; i += 256) {
        int c = i * 4;
        float4 v = *reinterpret_cast<const float4*>(row + Q_RANK + c);
        float4 w = *reinterpret_cast<const float4*>(wkv + c);
        float4 o;
        o.x = v.x * rkv * w.x;  o.y = v.y * rkv * w.y;
        o.z = v.z * rkv * w.z;  o.w = v.w * rkv * w.w;
        *reinterpret_cast<float4*>(out + OUT_KV + (size_t)m * KV_RANK + c) = o;
    }
    __syncthreads();

    if (tid < N_GROUPS) {
        float sc = fmaxf(s_amax[tid] / FP8_MAX, 1e-12f);
        s_amax[tid] = sc;
        out[OUT_SC + (size_t)m * N_GROUPS + tid] = sc;
    }
    __syncthreads();

    for (int i = tid; i < Q_RANK / 4; i += 256) {
        int c = i * 4;
        float inv = 1.0f / s_amax[c >> 7];
        float4 q = *reinterpret_cast<const float4*>(&s_qn[c]);
        float4 o;
        o.x = q.x * inv; o.y = q.y * inv; o.z = q.z * inv; o.w = q.w * inv;
        *reinterpret_cast<float4*>(out + OUT_QQ + (size_t)m * Q_RANK + c) = o;
    }
}

// ---------------------------------------------------------------------------
extern "C" void kernel_launch(void* const* d_in, const int* in_sizes, int n_in,
                              void* d_out, int out_size)
{
    const float* hidden = (const float*)d_in[0];   // [8192, 7168]
    const float* w_qkv  = (const float*)d_in[1];   // [7168, 2112]
    const float* wq     = (const float*)d_in[2];   // [1536]
    const float* wkv    = (const float*)d_in[3];   // [512]
    float* out = (float*)d_out;

    static bool attr_set = false;
    if (!attr_set) {
        cudaFuncSetAttribute(mma_gemm_kernel,
                             cudaFuncAttributeMaxDynamicSharedMemorySize, SMEM_TOTAL);
        attr_set = true;
    }

    conv_fused_kernel<<<(unsigned)(NBLK_A + NBLK_B), 256>>>(hidden, w_qkv);
    mma_gemm_kernel<<<dim3(N_PAD / NT, M_DIM / MT), 256, SMEM_TOTAL>>>();
    epilogue_kernel<<<M_DIM, 256>>>(wq, wkv, out);
}